// round 14
// baseline (speedup 1.0000x reference)
#include <cuda_runtime.h>
#include <cstdint>
#include <cstddef>

#define T_STEPS 32768
#define CD 512
#define ID 1024
#define NG 2048
#define NB   32           // CTAs
#define TPB  512          // threads per CTA
#define HPC  16           // h indices per CTA (one per warp)
#define KW   16           // ulonglong2 (4 floats) chunks per lane

// ---------------- device-global scratch ------------------------------------
__device__ float g_gx[(size_t)T_STEPS * NG];   // precomputed Wx@x + b, [T][2048]
// h publication: word j = (h_j bits) | (step tag << 32); warp-written, double buffered
__device__ unsigned long long g_hpub[2][CD];

// ---------------- morally-strong accessors ----------------------------------
__device__ __forceinline__ unsigned long long ld_acq64(const unsigned long long* p) {
    unsigned long long v;
    asm volatile("ld.acquire.gpu.global.b64 %0, [%1];" : "=l"(v) : "l"(p) : "memory");
    return v;
}
__device__ __forceinline__ void st_relax64(unsigned long long* p, unsigned long long v) {
    asm volatile("st.relaxed.gpu.global.b64 [%0], %1;" :: "l"(p), "l"(v) : "memory");
}

// ---------------- GEMM (+ inlined FULL state reset in block (0,0)) ----------
#define GBM 128
#define GBN 128
#define GBK 8

__global__ __launch_bounds__(256) void gemm_gx_kernel(
    const float* __restrict__ x,
    const float* __restrict__ wf_w, const float* __restrict__ wf_b,
    const float* __restrict__ wi_w, const float* __restrict__ wi_b,
    const float* __restrict__ wc_w, const float* __restrict__ wc_b,
    const float* __restrict__ wo_w, const float* __restrict__ wo_b)
{
    // ---- state reset: ALL 1024 tag words, strided (full clear every replay)
    if (blockIdx.x == 0 && blockIdx.y == 0) {
        for (int i = threadIdx.x; i < 2 * CD; i += 256)
            (&g_hpub[0][0])[i] = 0ull;   // h(0)=0, tag=0, both buffers
    }

    __shared__ float As[GBK][GBM];
    __shared__ float Bs[GBK][GBN];

    const int tid = threadIdx.x;
    const int tx = tid & 15;
    const int ty = tid >> 4;
    const int r0 = blockIdx.x * GBN;
    const int t0 = blockIdx.y * GBM;
    const int gate = r0 >> 9;
    const int rbase = r0 & 511;

    const float* wsrc = (gate == 0) ? wf_w : (gate == 1) ? wi_w : (gate == 2) ? wc_w : wo_w;
    const float* bsrc = (gate == 0) ? wf_b : (gate == 1) ? wi_b : (gate == 2) ? wc_b : wo_b;

    const int lrow = tid >> 1;
    const int lk4  = (tid & 1) * 4;

    float acc[8][8];
    #pragma unroll
    for (int i = 0; i < 8; i++)
        #pragma unroll
        for (int j = 0; j < 8; j++) acc[i][j] = 0.0f;

    for (int k0 = 0; k0 < CD; k0 += GBK) {
        float4 av = *(const float4*)(x    + (size_t)(t0 + lrow) * CD + k0 + lk4);
        float4 bv = *(const float4*)(wsrc + (size_t)(rbase + lrow) * ID + k0 + lk4);
        __syncthreads();
        As[lk4 + 0][lrow] = av.x; As[lk4 + 1][lrow] = av.y;
        As[lk4 + 2][lrow] = av.z; As[lk4 + 3][lrow] = av.w;
        Bs[lk4 + 0][lrow] = bv.x; Bs[lk4 + 1][lrow] = bv.y;
        Bs[lk4 + 2][lrow] = bv.z; Bs[lk4 + 3][lrow] = bv.w;
        __syncthreads();
        #pragma unroll
        for (int k = 0; k < GBK; k++) {
            const float4* As4 = (const float4*)As[k];
            const float4* Bs4 = (const float4*)Bs[k];
            float4 a0 = As4[ty], a1 = As4[16 + ty];
            float4 b0 = Bs4[tx], b1 = Bs4[16 + tx];
            float ar[8] = {a0.x, a0.y, a0.z, a0.w, a1.x, a1.y, a1.z, a1.w};
            float br[8] = {b0.x, b0.y, b0.z, b0.w, b1.x, b1.y, b1.z, b1.w};
            #pragma unroll
            for (int i = 0; i < 8; i++)
                #pragma unroll
                for (int j = 0; j < 8; j++) acc[i][j] += ar[i] * br[j];
        }
    }

    float4 bias0 = *(const float4*)(bsrc + rbase + tx * 4);
    float4 bias1 = *(const float4*)(bsrc + rbase + 64 + tx * 4);
    float bb[8] = {bias0.x, bias0.y, bias0.z, bias0.w, bias1.x, bias1.y, bias1.z, bias1.w};

    #pragma unroll
    for (int i = 0; i < 8; i++) {
        int trow = t0 + ((i < 4) ? (ty * 4 + i) : (64 + ty * 4 + i - 4));
        float4 o0, o1;
        o0.x = acc[i][0] + bb[0]; o0.y = acc[i][1] + bb[1];
        o0.z = acc[i][2] + bb[2]; o0.w = acc[i][3] + bb[3];
        o1.x = acc[i][4] + bb[4]; o1.y = acc[i][5] + bb[5];
        o1.z = acc[i][6] + bb[6]; o1.w = acc[i][7] + bb[7];
        *(float4*)(g_gx + (size_t)trow * NG + r0 + tx * 4)      = o0;
        *(float4*)(g_gx + (size_t)trow * NG + r0 + 64 + tx * 4) = o1;
    }
}

// ---------------- persistent recurrent kernel --------------------------------
__device__ __forceinline__ unsigned long long ffma2(
    unsigned long long a, unsigned long long b, unsigned long long c) {
    unsigned long long d;
    asm ("fma.rn.f32x2 %0, %1, %2, %3;" : "=l"(d) : "l"(a), "l"(b), "l"(c));
    return d;
}
__device__ __forceinline__ float2 unpack2(unsigned long long a) {
    float2 r;
    asm ("mov.b64 {%0, %1}, %2;" : "=f"(r.x), "=f"(r.y) : "l"(a));
    return r;
}
__device__ __forceinline__ float sigmoid_f(float x) {
    return __fdividef(1.0f, 1.0f + __expf(-x));
}
__device__ __forceinline__ float tanh_f(float x) {
    float ax = fabsf(x);
    float e  = __expf(-2.0f * ax);
    float t  = __fdividef(1.0f - e, 1.0f + e);
    return copysignf(t, x);
}

// Layout: warp w of CTA cta owns h index j = cta*16 + w.
// Within the warp: lane = gate*8 + c (gate 0..3, c = k-lane 0..7).
// Each lane: 64-MAC partial dot of row (gate, j) against h(t).
__global__ __launch_bounds__(TPB, 1) void lstm_rec_kernel(
    const float* __restrict__ wf_w, const float* __restrict__ wi_w,
    const float* __restrict__ wc_w, const float* __restrict__ wo_w,
    float* __restrict__ d_out)
{
    __shared__ __align__(16) float hsf[CD];   // h(t) broadcast

    const ulonglong2* hs = (const ulonglong2*)hsf;

    const int tid  = threadIdx.x;
    const int wid  = tid >> 5;          // warp = local h index 0..15
    const int lane = tid & 31;
    const int gate = lane >> 3;
    const int c    = lane & 7;
    const int cta  = blockIdx.x;
    const int j    = cta * HPC + wid;   // global h index this warp owns
    const bool glane = (c == 0);        // 4 gate-lanes per warp (0,8,16,24)

    // ---- this lane's 64 h-part weights in registers (16 x ulonglong2)
    const float* wsrc = (gate == 0) ? wf_w : (gate == 1) ? wi_w : (gate == 2) ? wc_w : wo_w;
    const ulonglong2* wp = (const ulonglong2*)(wsrc + (size_t)j * ID + CD);
    ulonglong2 wv[KW];
    #pragma unroll
    for (int kk = 0; kk < KW; kk++) wv[kk] = wp[c + 8 * kk];

    // ---- gate-lanes prefetch their own gx value
    const float* gxrow = g_gx + (size_t)gate * CD + j;
    float gx_cur = glane ? __ldcs(gxrow) : 0.0f;

    float c_state = 0.0f;   // live in lane 0 of each warp
    float h_last  = 0.0f;

    for (int t = 0; t < T_STEPS; t++) {
        const int b  = t & 1;
        const int b2 = (t + 1) & 1;
        const unsigned int ut = (unsigned int)t;

        // ---- prefetch next step's gx (flies during the poll)
        float gx_next = 0.0f;
        if (glane && (t + 1) < T_STEPS)
            gx_next = __ldcs(gxrow + (size_t)(t + 1) * NG);

        // ---- single-RTT detect+gather: each thread polls exactly ONE word
        const unsigned long long* w0 = &g_hpub[b][tid];
        unsigned long long v = ld_acq64(w0);
        while ((unsigned)(v >> 32) != ut) v = ld_acq64(w0);
        hsf[tid] = __uint_as_float((unsigned)v);
        __syncthreads();                                  // bar1: h(t) in smem

        // ---- recurrent dot: 64 MACs via 32 packed f32x2 FMAs
        unsigned long long a0 = 0ull, a1 = 0ull, a2 = 0ull, a3 = 0ull;
        #pragma unroll
        for (int kk = 0; kk < KW; kk += 2) {
            ulonglong2 h0 = hs[c + 8 * kk];
            ulonglong2 h1 = hs[c + 8 * (kk + 1)];
            a0 = ffma2(wv[kk].x,     h0.x, a0);
            a1 = ffma2(wv[kk].y,     h0.y, a1);
            a2 = ffma2(wv[kk + 1].x, h1.x, a2);
            a3 = ffma2(wv[kk + 1].y, h1.y, a3);
        }
        float2 u0 = unpack2(a0), u1 = unpack2(a1), u2 = unpack2(a2), u3 = unpack2(a3);
        float acc = ((u0.x + u0.y) + (u1.x + u1.y)) + ((u2.x + u2.y) + (u3.x + u3.y));
        // reduce each 8-lane gate group (valid at lanes 0,8,16,24)
        acc += __shfl_down_sync(0xffffffffu, acc, 4);
        acc += __shfl_down_sync(0xffffffffu, acc, 2);
        acc += __shfl_down_sync(0xffffffffu, acc, 1);

        // ---- activations in PARALLEL on the 4 gate-lanes (no smem, no bar)
        float act = 0.0f;
        if (glane) {
            float g = acc + gx_cur;
            act = (gate == 2) ? tanh_f(g) : sigmoid_f(g);
            gx_cur = gx_next;
        }
        float f  = __shfl_sync(0xffffffffu, act, 0);
        float ii = __shfl_sync(0xffffffffu, act, 8);
        float cc = __shfl_sync(0xffffffffu, act, 16);
        float oo = __shfl_sync(0xffffffffu, act, 24);

        // ---- state update + one-store publish (lane 0 of each warp)
        if (lane == 0) {
            c_state = f * c_state + ii * cc;
            h_last  = tanh_f(c_state) * oo;
            unsigned long long pv = (unsigned long long)__float_as_uint(h_last)
                                  | ((unsigned long long)(ut + 1u) << 32);
            st_relax64(&g_hpub[b2][j], pv);               // data + tag, one store
        }
        // no trailing barrier: next poll is the global step barrier
    }

    if (lane == 0) {
        d_out[j]      = c_state;   // output = (c, h)
        d_out[CD + j] = h_last;
    }
}

// ---------------- launch -----------------------------------------------------
extern "C" void kernel_launch(void* const* d_in, const int* in_sizes, int n_in,
                              void* d_out, int out_size) {
    (void)in_sizes; (void)n_in; (void)out_size;
    const float* x    = (const float*)d_in[0];
    const float* wf_w = (const float*)d_in[1];
    const float* wf_b = (const float*)d_in[2];
    const float* wi_w = (const float*)d_in[3];
    const float* wi_b = (const float*)d_in[4];
    const float* wc_w = (const float*)d_in[5];
    const float* wc_b = (const float*)d_in[6];
    const float* wo_w = (const float*)d_in[7];
    const float* wo_b = (const float*)d_in[8];
    float* out = (float*)d_out;

    dim3 ggrid(NG / GBN, T_STEPS / GBM);
    gemm_gx_kernel<<<ggrid, 256>>>(x, wf_w, wf_b, wi_w, wi_b, wc_w, wc_b, wo_w, wo_b);

    lstm_rec_kernel<<<NB, TPB>>>(wf_w, wi_w, wc_w, wo_w, out);
}

// round 15
// speedup vs baseline: 1.0249x; 1.0249x over previous
#include <cuda_runtime.h>
#include <cstdint>
#include <cstddef>

#define T_STEPS 32768
#define CD 512
#define ID 1024
#define NG 2048
#define NB   64           // CTAs
#define TPB  256          // threads per CTA (8 warps)
#define HPC  8            // h indices per CTA (one per warp)
#define KW   16           // ulonglong2 (4 floats) chunks per lane

// ---------------- device-global scratch ------------------------------------
__device__ float g_gx[(size_t)T_STEPS * NG];   // precomputed Wx@x + b, [T][2048]
// h publication: word j = (h_j bits) | (step tag << 32); warp-written, double buffered
__device__ unsigned long long g_hpub[2][CD];

// ---------------- morally-strong accessors ----------------------------------
__device__ __forceinline__ unsigned long long ld_acq64(const unsigned long long* p) {
    unsigned long long v;
    asm volatile("ld.acquire.gpu.global.b64 %0, [%1];" : "=l"(v) : "l"(p) : "memory");
    return v;
}
__device__ __forceinline__ void st_relax64(unsigned long long* p, unsigned long long v) {
    asm volatile("st.relaxed.gpu.global.b64 [%0], %1;" :: "l"(p), "l"(v) : "memory");
}

// ---------------- GEMM (+ inlined FULL state reset in block (0,0)) ----------
#define GBM 128
#define GBN 128
#define GBK 8

__global__ __launch_bounds__(256) void gemm_gx_kernel(
    const float* __restrict__ x,
    const float* __restrict__ wf_w, const float* __restrict__ wf_b,
    const float* __restrict__ wi_w, const float* __restrict__ wi_b,
    const float* __restrict__ wc_w, const float* __restrict__ wc_b,
    const float* __restrict__ wo_w, const float* __restrict__ wo_b)
{
    // ---- state reset: ALL 1024 tag words, strided (full clear every replay)
    if (blockIdx.x == 0 && blockIdx.y == 0) {
        for (int i = threadIdx.x; i < 2 * CD; i += 256)
            (&g_hpub[0][0])[i] = 0ull;   // h(0)=0, tag=0, both buffers
    }

    __shared__ float As[GBK][GBM];
    __shared__ float Bs[GBK][GBN];

    const int tid = threadIdx.x;
    const int tx = tid & 15;
    const int ty = tid >> 4;
    const int r0 = blockIdx.x * GBN;
    const int t0 = blockIdx.y * GBM;
    const int gate = r0 >> 9;
    const int rbase = r0 & 511;

    const float* wsrc = (gate == 0) ? wf_w : (gate == 1) ? wi_w : (gate == 2) ? wc_w : wo_w;
    const float* bsrc = (gate == 0) ? wf_b : (gate == 1) ? wi_b : (gate == 2) ? wc_b : wo_b;

    const int lrow = tid >> 1;
    const int lk4  = (tid & 1) * 4;

    float acc[8][8];
    #pragma unroll
    for (int i = 0; i < 8; i++)
        #pragma unroll
        for (int j = 0; j < 8; j++) acc[i][j] = 0.0f;

    for (int k0 = 0; k0 < CD; k0 += GBK) {
        float4 av = *(const float4*)(x    + (size_t)(t0 + lrow) * CD + k0 + lk4);
        float4 bv = *(const float4*)(wsrc + (size_t)(rbase + lrow) * ID + k0 + lk4);
        __syncthreads();
        As[lk4 + 0][lrow] = av.x; As[lk4 + 1][lrow] = av.y;
        As[lk4 + 2][lrow] = av.z; As[lk4 + 3][lrow] = av.w;
        Bs[lk4 + 0][lrow] = bv.x; Bs[lk4 + 1][lrow] = bv.y;
        Bs[lk4 + 2][lrow] = bv.z; Bs[lk4 + 3][lrow] = bv.w;
        __syncthreads();
        #pragma unroll
        for (int k = 0; k < GBK; k++) {
            const float4* As4 = (const float4*)As[k];
            const float4* Bs4 = (const float4*)Bs[k];
            float4 a0 = As4[ty], a1 = As4[16 + ty];
            float4 b0 = Bs4[tx], b1 = Bs4[16 + tx];
            float ar[8] = {a0.x, a0.y, a0.z, a0.w, a1.x, a1.y, a1.z, a1.w};
            float br[8] = {b0.x, b0.y, b0.z, b0.w, b1.x, b1.y, b1.z, b1.w};
            #pragma unroll
            for (int i = 0; i < 8; i++)
                #pragma unroll
                for (int j = 0; j < 8; j++) acc[i][j] += ar[i] * br[j];
        }
    }

    float4 bias0 = *(const float4*)(bsrc + rbase + tx * 4);
    float4 bias1 = *(const float4*)(bsrc + rbase + 64 + tx * 4);
    float bb[8] = {bias0.x, bias0.y, bias0.z, bias0.w, bias1.x, bias1.y, bias1.z, bias1.w};

    #pragma unroll
    for (int i = 0; i < 8; i++) {
        int trow = t0 + ((i < 4) ? (ty * 4 + i) : (64 + ty * 4 + i - 4));
        float4 o0, o1;
        o0.x = acc[i][0] + bb[0]; o0.y = acc[i][1] + bb[1];
        o0.z = acc[i][2] + bb[2]; o0.w = acc[i][3] + bb[3];
        o1.x = acc[i][4] + bb[4]; o1.y = acc[i][5] + bb[5];
        o1.z = acc[i][6] + bb[6]; o1.w = acc[i][7] + bb[7];
        *(float4*)(g_gx + (size_t)trow * NG + r0 + tx * 4)      = o0;
        *(float4*)(g_gx + (size_t)trow * NG + r0 + 64 + tx * 4) = o1;
    }
}

// ---------------- persistent recurrent kernel --------------------------------
__device__ __forceinline__ unsigned long long ffma2(
    unsigned long long a, unsigned long long b, unsigned long long c) {
    unsigned long long d;
    asm ("fma.rn.f32x2 %0, %1, %2, %3;" : "=l"(d) : "l"(a), "l"(b), "l"(c));
    return d;
}
__device__ __forceinline__ float2 unpack2(unsigned long long a) {
    float2 r;
    asm ("mov.b64 {%0, %1}, %2;" : "=f"(r.x), "=f"(r.y) : "l"(a));
    return r;
}
__device__ __forceinline__ float sigmoid_f(float x) {
    return __fdividef(1.0f, 1.0f + __expf(-x));
}
__device__ __forceinline__ float tanh_f(float x) {
    float ax = fabsf(x);
    float e  = __expf(-2.0f * ax);
    float t  = __fdividef(1.0f - e, 1.0f + e);
    return copysignf(t, x);
}

// Layout: warp w of CTA cta owns h index j = cta*8 + w.
// Within the warp: lane = gate*8 + c (gate 0..3, c = k-lane 0..7).
// Each lane: 64-MAC partial dot of row (gate, j) against h(t).
__global__ __launch_bounds__(TPB, 1) void lstm_rec_kernel(
    const float* __restrict__ wf_w, const float* __restrict__ wi_w,
    const float* __restrict__ wc_w, const float* __restrict__ wo_w,
    float* __restrict__ d_out)
{
    __shared__ __align__(16) float hsf[CD];   // h(t) broadcast

    const ulonglong2* hs = (const ulonglong2*)hsf;
    unsigned long long* hsll = (unsigned long long*)hsf;

    const int tid  = threadIdx.x;
    const int wid  = tid >> 5;          // warp = local h index 0..7
    const int lane = tid & 31;
    const int gate = lane >> 3;
    const int c    = lane & 7;
    const int cta  = blockIdx.x;
    const int j    = cta * HPC + wid;   // global h index this warp owns
    const bool glane = (c == 0);        // 4 gate-lanes per warp (0,8,16,24)

    // ---- this lane's 64 h-part weights in registers (16 x ulonglong2)
    const float* wsrc = (gate == 0) ? wf_w : (gate == 1) ? wi_w : (gate == 2) ? wc_w : wo_w;
    const ulonglong2* wp = (const ulonglong2*)(wsrc + (size_t)j * ID + CD);
    ulonglong2 wv[KW];
    #pragma unroll
    for (int kk = 0; kk < KW; kk++) wv[kk] = wp[c + 8 * kk];

    // ---- gate-lanes prefetch their own gx value
    const float* gxrow = g_gx + (size_t)gate * CD + j;
    float gx_cur = glane ? __ldcs(gxrow) : 0.0f;

    float c_state = 0.0f;   // live in lane 0 of each warp
    float h_last  = 0.0f;

    for (int t = 0; t < T_STEPS; t++) {
        const int b  = t & 1;
        const int b2 = (t + 1) & 1;
        const unsigned int ut = (unsigned int)t;

        // ---- prefetch next step's gx (flies during the poll)
        float gx_next = 0.0f;
        if (glane && (t + 1) < T_STEPS)
            gx_next = __ldcs(gxrow + (size_t)(t + 1) * NG);

        // ---- single-RTT detect+gather: poll BOTH words each iteration (MLP=2)
        const unsigned long long* w0 = &g_hpub[b][2 * tid];
        unsigned long long v0 = ld_acq64(w0);
        unsigned long long v1 = ld_acq64(w0 + 1);
        while (((unsigned)(v0 >> 32) != ut) | ((unsigned)(v1 >> 32) != ut)) {
            v0 = ld_acq64(w0);
            v1 = ld_acq64(w0 + 1);
        }
        hsll[tid] = (v0 & 0xffffffffull) | (v1 << 32);   // STS.64: two h floats
        __syncthreads();                                  // bar1: h(t) in smem

        // ---- recurrent dot: 64 MACs via 32 packed f32x2 FMAs
        unsigned long long a0 = 0ull, a1 = 0ull, a2 = 0ull, a3 = 0ull;
        #pragma unroll
        for (int kk = 0; kk < KW; kk += 2) {
            ulonglong2 h0 = hs[c + 8 * kk];
            ulonglong2 h1 = hs[c + 8 * (kk + 1)];
            a0 = ffma2(wv[kk].x,     h0.x, a0);
            a1 = ffma2(wv[kk].y,     h0.y, a1);
            a2 = ffma2(wv[kk + 1].x, h1.x, a2);
            a3 = ffma2(wv[kk + 1].y, h1.y, a3);
        }
        float2 u0 = unpack2(a0), u1 = unpack2(a1), u2 = unpack2(a2), u3 = unpack2(a3);
        float acc = ((u0.x + u0.y) + (u1.x + u1.y)) + ((u2.x + u2.y) + (u3.x + u3.y));
        // reduce each 8-lane gate group (valid at lanes 0,8,16,24)
        acc += __shfl_down_sync(0xffffffffu, acc, 4);
        acc += __shfl_down_sync(0xffffffffu, acc, 2);
        acc += __shfl_down_sync(0xffffffffu, acc, 1);

        // ---- activations in PARALLEL on the 4 gate-lanes (no smem, no bar)
        float act = 0.0f;
        if (glane) {
            float g = acc + gx_cur;
            act = (gate == 2) ? tanh_f(g) : sigmoid_f(g);
            gx_cur = gx_next;
        }
        float f  = __shfl_sync(0xffffffffu, act, 0);
        float ii = __shfl_sync(0xffffffffu, act, 8);
        float cc = __shfl_sync(0xffffffffu, act, 16);
        float oo = __shfl_sync(0xffffffffu, act, 24);

        // ---- state update + one-store publish (lane 0 of each warp)
        if (lane == 0) {
            c_state = f * c_state + ii * cc;
            h_last  = tanh_f(c_state) * oo;
            unsigned long long pv = (unsigned long long)__float_as_uint(h_last)
                                  | ((unsigned long long)(ut + 1u) << 32);
            st_relax64(&g_hpub[b2][j], pv);               // data + tag, one store
        }
        // no trailing barrier: next poll is the global step barrier
    }

    if (lane == 0) {
        d_out[j]      = c_state;   // output = (c, h)
        d_out[CD + j] = h_last;
    }
}

// ---------------- launch -----------------------------------------------------
extern "C" void kernel_launch(void* const* d_in, const int* in_sizes, int n_in,
                              void* d_out, int out_size) {
    (void)in_sizes; (void)n_in; (void)out_size;
    const float* x    = (const float*)d_in[0];
    const float* wf_w = (const float*)d_in[1];
    const float* wf_b = (const float*)d_in[2];
    const float* wi_w = (const float*)d_in[3];
    const float* wi_b = (const float*)d_in[4];
    const float* wc_w = (const float*)d_in[5];
    const float* wc_b = (const float*)d_in[6];
    const float* wo_w = (const float*)d_in[7];
    const float* wo_b = (const float*)d_in[8];
    float* out = (float*)d_out;

    dim3 ggrid(NG / GBN, T_STEPS / GBM);
    gemm_gx_kernel<<<ggrid, 256>>>(x, wf_w, wf_b, wi_w, wi_b, wc_w, wc_b, wo_w, wo_b);

    lstm_rec_kernel<<<NB, TPB>>>(wf_w, wi_w, wc_w, wo_w, out);
}

// round 16
// speedup vs baseline: 1.1815x; 1.1527x over previous
#include <cuda_runtime.h>
#include <cstdint>
#include <cstddef>

#define T_STEPS 32768
#define CD 512
#define ID 1024
#define NG 2048
#define NB   64
#define TPB  256
#define JPB  8            // h indices per CTA
#define NROWS 32          // 4 gates * JPB rows per CTA
#define KW   16           // ulonglong2 (4 floats) chunks per lane

// ---------------- device-global scratch ------------------------------------
__device__ float g_gx[(size_t)T_STEPS * NG];   // precomputed Wx@x + b, [T][2048]
// h publication: word j = (h_j bits) | (step tag << 32); owner-written, double buffered
__device__ unsigned long long g_hpub[2][CD];

// ---------------- morally-strong accessors ----------------------------------
__device__ __forceinline__ unsigned long long ld_acq64(const unsigned long long* p) {
    unsigned long long v;
    asm volatile("ld.acquire.gpu.global.b64 %0, [%1];" : "=l"(v) : "l"(p) : "memory");
    return v;
}
__device__ __forceinline__ void st_relax64(unsigned long long* p, unsigned long long v) {
    asm volatile("st.relaxed.gpu.global.b64 [%0], %1;" :: "l"(p), "l"(v) : "memory");
}

// ---------------- GEMM (+ inlined FULL state reset in block (0,0)) ----------
#define GBM 128
#define GBN 128
#define GBK 8

__global__ __launch_bounds__(256) void gemm_gx_kernel(
    const float* __restrict__ x,
    const float* __restrict__ wf_w, const float* __restrict__ wf_b,
    const float* __restrict__ wi_w, const float* __restrict__ wi_b,
    const float* __restrict__ wc_w, const float* __restrict__ wc_b,
    const float* __restrict__ wo_w, const float* __restrict__ wo_b)
{
    // ---- state reset: ALL 1024 tag words, strided (full clear every replay)
    if (blockIdx.x == 0 && blockIdx.y == 0) {
        for (int i = threadIdx.x; i < 2 * CD; i += 256)
            (&g_hpub[0][0])[i] = 0ull;   // h(0)=0, tag=0, both buffers
    }

    __shared__ float As[GBK][GBM];
    __shared__ float Bs[GBK][GBN];

    const int tid = threadIdx.x;
    const int tx = tid & 15;
    const int ty = tid >> 4;
    const int r0 = blockIdx.x * GBN;
    const int t0 = blockIdx.y * GBM;
    const int gate = r0 >> 9;
    const int rbase = r0 & 511;

    const float* wsrc = (gate == 0) ? wf_w : (gate == 1) ? wi_w : (gate == 2) ? wc_w : wo_w;
    const float* bsrc = (gate == 0) ? wf_b : (gate == 1) ? wi_b : (gate == 2) ? wc_b : wo_b;

    const int lrow = tid >> 1;
    const int lk4  = (tid & 1) * 4;

    float acc[8][8];
    #pragma unroll
    for (int i = 0; i < 8; i++)
        #pragma unroll
        for (int j = 0; j < 8; j++) acc[i][j] = 0.0f;

    for (int k0 = 0; k0 < CD; k0 += GBK) {
        float4 av = *(const float4*)(x    + (size_t)(t0 + lrow) * CD + k0 + lk4);
        float4 bv = *(const float4*)(wsrc + (size_t)(rbase + lrow) * ID + k0 + lk4);
        __syncthreads();
        As[lk4 + 0][lrow] = av.x; As[lk4 + 1][lrow] = av.y;
        As[lk4 + 2][lrow] = av.z; As[lk4 + 3][lrow] = av.w;
        Bs[lk4 + 0][lrow] = bv.x; Bs[lk4 + 1][lrow] = bv.y;
        Bs[lk4 + 2][lrow] = bv.z; Bs[lk4 + 3][lrow] = bv.w;
        __syncthreads();
        #pragma unroll
        for (int k = 0; k < GBK; k++) {
            const float4* As4 = (const float4*)As[k];
            const float4* Bs4 = (const float4*)Bs[k];
            float4 a0 = As4[ty], a1 = As4[16 + ty];
            float4 b0 = Bs4[tx], b1 = Bs4[16 + tx];
            float ar[8] = {a0.x, a0.y, a0.z, a0.w, a1.x, a1.y, a1.z, a1.w};
            float br[8] = {b0.x, b0.y, b0.z, b0.w, b1.x, b1.y, b1.z, b1.w};
            #pragma unroll
            for (int i = 0; i < 8; i++)
                #pragma unroll
                for (int j = 0; j < 8; j++) acc[i][j] += ar[i] * br[j];
        }
    }

    float4 bias0 = *(const float4*)(bsrc + rbase + tx * 4);
    float4 bias1 = *(const float4*)(bsrc + rbase + 64 + tx * 4);
    float bb[8] = {bias0.x, bias0.y, bias0.z, bias0.w, bias1.x, bias1.y, bias1.z, bias1.w};

    #pragma unroll
    for (int i = 0; i < 8; i++) {
        int trow = t0 + ((i < 4) ? (ty * 4 + i) : (64 + ty * 4 + i - 4));
        float4 o0, o1;
        o0.x = acc[i][0] + bb[0]; o0.y = acc[i][1] + bb[1];
        o0.z = acc[i][2] + bb[2]; o0.w = acc[i][3] + bb[3];
        o1.x = acc[i][4] + bb[4]; o1.y = acc[i][5] + bb[5];
        o1.z = acc[i][6] + bb[6]; o1.w = acc[i][7] + bb[7];
        *(float4*)(g_gx + (size_t)trow * NG + r0 + tx * 4)      = o0;
        *(float4*)(g_gx + (size_t)trow * NG + r0 + 64 + tx * 4) = o1;
    }
}

// ---------------- persistent recurrent kernel --------------------------------
__device__ __forceinline__ unsigned long long ffma2(
    unsigned long long a, unsigned long long b, unsigned long long c) {
    unsigned long long d;
    asm ("fma.rn.f32x2 %0, %1, %2, %3;" : "=l"(d) : "l"(a), "l"(b), "l"(c));
    return d;
}
__device__ __forceinline__ float2 unpack2(unsigned long long a) {
    float2 r;
    asm ("mov.b64 {%0, %1}, %2;" : "=f"(r.x), "=f"(r.y) : "l"(a));
    return r;
}
__device__ __forceinline__ float sigmoid_f(float x) {
    return __fdividef(1.0f, 1.0f + __expf(-x));
}
__device__ __forceinline__ float tanh_f(float x) {
    float ax = fabsf(x);
    float e  = __expf(-2.0f * ax);
    float t  = __fdividef(1.0f - e, 1.0f + e);
    return copysignf(t, x);
}

__global__ __launch_bounds__(TPB, 1) void lstm_rec_kernel(
    const float* __restrict__ wf_w, const float* __restrict__ wi_w,
    const float* __restrict__ wc_w, const float* __restrict__ wo_w,
    float* __restrict__ d_out)
{
    __shared__ __align__(16) float hsf[CD];   // h(t) broadcast
    __shared__ float gsm[NROWS];              // ACTIVATED per-row gate values

    const ulonglong2* hs = (const ulonglong2*)hsf;
    unsigned long long* hsll = (unsigned long long*)hsf;

    const int tid  = threadIdx.x;
    const int r    = tid >> 3;          // local row 0..31
    const int c    = tid & 7;           // lane within row
    const int gate = r >> 3;
    const int jj   = r & 7;
    const int cta  = blockIdx.x;
    const int j0   = cta * JPB;
    const bool rowner = (c == 0);       // 32 row-owner threads (activations)
    const bool owner  = (tid < JPB);    // 8 h-owner threads (state + publish)

    // ---- this thread's 64 h-part weights in registers (16 x ulonglong2)
    const float* wsrc = (gate == 0) ? wf_w : (gate == 1) ? wi_w : (gate == 2) ? wc_w : wo_w;
    const ulonglong2* wp = (const ulonglong2*)(wsrc + (size_t)(j0 + jj) * ID + CD);
    ulonglong2 wv[KW];
    #pragma unroll
    for (int kk = 0; kk < KW; kk++) wv[kk] = wp[c + 8 * kk];

    // ---- per-ROW gx pointer (32 row-owners each prefetch their own gate value)
    const float* gxrow = g_gx + (size_t)gate * CD + j0 + jj;
    float gx_cur = rowner ? __ldcs(gxrow) : 0.0f;

    float c_state = 0.0f;
    float h_last  = 0.0f;

    for (int t = 0; t < T_STEPS; t++) {
        const int b  = t & 1;
        const int b2 = (t + 1) & 1;
        const unsigned int ut = (unsigned int)t;

        // ---- prefetch next step's gx (flies during the poll)
        float gx_next = 0.0f;
        if (rowner && (t + 1) < T_STEPS)
            gx_next = __ldcs(gxrow + (size_t)(t + 1) * NG);

        // ---- single-RTT detect+gather with 2-deep PIPELINED polling:
        // wave k is checked while wave k+1 is already in flight, halving the
        // sampling period (detect lag and cross-CTA phase spread shrink).
        const unsigned long long* w0 = &g_hpub[b][2 * tid];
        unsigned long long v0 = ld_acq64(w0);
        unsigned long long v1 = ld_acq64(w0 + 1);
        unsigned long long p0 = ld_acq64(w0);
        unsigned long long p1 = ld_acq64(w0 + 1);
        while (((unsigned)(v0 >> 32) != ut) | ((unsigned)(v1 >> 32) != ut)) {
            v0 = p0;                 // rotate: next wave becomes current
            v1 = p1;
            p0 = ld_acq64(w0);       // re-issue the in-flight wave
            p1 = ld_acq64(w0 + 1);
        }
        hsll[tid] = (v0 & 0xffffffffull) | (v1 << 32);   // STS.64: two h floats
        __syncthreads();                                  // bar1: h(t) in smem

        // ---- recurrent dot: 64 MACs via 32 packed f32x2 FMAs
        unsigned long long a0 = 0ull, a1 = 0ull, a2 = 0ull, a3 = 0ull;
        #pragma unroll
        for (int kk = 0; kk < KW; kk += 2) {
            ulonglong2 h0 = hs[c + 8 * kk];
            ulonglong2 h1 = hs[c + 8 * (kk + 1)];
            a0 = ffma2(wv[kk].x,     h0.x, a0);
            a1 = ffma2(wv[kk].y,     h0.y, a1);
            a2 = ffma2(wv[kk + 1].x, h1.x, a2);
            a3 = ffma2(wv[kk + 1].y, h1.y, a3);
        }
        float2 u0 = unpack2(a0), u1 = unpack2(a1), u2 = unpack2(a2), u3 = unpack2(a3);
        float acc = ((u0.x + u0.y) + (u1.x + u1.y)) + ((u2.x + u2.y) + (u3.x + u3.y));
        acc += __shfl_down_sync(0xffffffffu, acc, 4);
        acc += __shfl_down_sync(0xffffffffu, acc, 2);
        acc += __shfl_down_sync(0xffffffffu, acc, 1);

        // ---- parallel activations: 32 row-owners activate their gate value
        if (rowner) {
            float g = acc + gx_cur;
            gsm[r] = (gate == 2) ? tanh_f(g) : sigmoid_f(g);
            gx_cur = gx_next;
        }
        __syncthreads();                                  // bar2: activated gates ready

        // ---- state update + one-store publish (8 owner threads)
        if (owner) {
            float f  = gsm[tid];
            float ii = gsm[ 8 + tid];
            float cc = gsm[16 + tid];
            float oo = gsm[24 + tid];
            c_state = f * c_state + ii * cc;
            h_last  = tanh_f(c_state) * oo;
            unsigned long long pv = (unsigned long long)__float_as_uint(h_last)
                                  | ((unsigned long long)(ut + 1u) << 32);
            st_relax64(&g_hpub[b2][j0 + tid], pv);        // data + tag, one store
        }
        // no trailing barrier: next poll is the global step barrier
    }

    if (owner) {
        d_out[j0 + tid]      = c_state;   // output = (c, h)
        d_out[CD + j0 + tid] = h_last;
    }
}

// ---------------- launch -----------------------------------------------------
extern "C" void kernel_launch(void* const* d_in, const int* in_sizes, int n_in,
                              void* d_out, int out_size) {
    (void)in_sizes; (void)n_in; (void)out_size;
    const float* x    = (const float*)d_in[0];
    const float* wf_w = (const float*)d_in[1];
    const float* wf_b = (const float*)d_in[2];
    const float* wi_w = (const float*)d_in[3];
    const float* wi_b = (const float*)d_in[4];
    const float* wc_w = (const float*)d_in[5];
    const float* wc_b = (const float*)d_in[6];
    const float* wo_w = (const float*)d_in[7];
    const float* wo_b = (const float*)d_in[8];
    float* out = (float*)d_out;

    dim3 ggrid(NG / GBN, T_STEPS / GBM);
    gemm_gx_kernel<<<ggrid, 256>>>(x, wf_w, wf_b, wi_w, wi_b, wc_w, wc_b, wo_w, wo_b);

    lstm_rec_kernel<<<NB, TPB>>>(wf_w, wi_w, wc_w, wo_w, out);
}